// round 8
// baseline (speedup 1.0000x reference)
#include <cuda_runtime.h>
#include <math.h>
#include <stdint.h>

#define UNITS     128
#define N_ITER    10
#define BXS       10
#define NTHREADS  256

// ---- blocks_kernel smem (bytes) ----
#define BUFX_BYTE  0         // 128*10*4 = 5120
#define ZBH0_BYTE  5120
#define ZBL0_BYTE  7168
#define ZBH1_BYTE  9216
#define ZBL1_BYTE  11264
#define WLS_BYTE   13312     // 32768
#define K2_SMEM_BYTES 46080

// pre-split weights (bf16 raw bits): W_in [128*784], then W1..W4 [128*128] each
#define WIN_ELEMS  (128 * 784)
#define WB_ELEMS   (128 * 128)
#define TOT_ELEMS  (WIN_ELEMS + 4 * WB_ELEMS)
__device__ unsigned short g_wh[TOT_ELEMS];
__device__ unsigned short g_wl[TOT_ELEMS];

__device__ __forceinline__ uint32_t smem_u32(const void* p) {
    uint32_t a;
    asm("{ .reg .u64 t; cvta.to.shared.u64 t, %1; cvt.u32.u64 %0, t; }" : "=r"(a) : "l"(p));
    return a;
}
__device__ __forceinline__ float fast_tanh(float x) {
    float e, r;
    asm("ex2.approx.f32 %0, %1;" : "=f"(e) : "f"(x * 2.8853900817779268f));
    asm("rcp.approx.f32 %0, %1;" : "=f"(r) : "f"(e + 1.0f));
    return fmaf(-2.0f, r, 1.0f);
}
__device__ __forceinline__ uint32_t bfpack(float lo, float hi) {
    uint32_t r;
    asm("cvt.rn.bf16x2.f32 %0, %1, %2;" : "=r"(r) : "f"(hi), "f"(lo));
    return r;
}
__device__ __forceinline__ unsigned short f2bf(float f) {
    unsigned short h;
    asm("cvt.rn.bf16.f32 %0, %1;" : "=h"(h) : "f"(f));
    return h;
}
__device__ __forceinline__ void mma_bf16(float* c,
                                         uint32_t a0, uint32_t a1, uint32_t a2, uint32_t a3,
                                         uint32_t b0, uint32_t b1) {
    asm volatile(
        "mma.sync.aligned.m16n8k16.row.col.f32.bf16.bf16.f32 "
        "{%0,%1,%2,%3}, {%4,%5,%6,%7}, {%8,%9}, {%0,%1,%2,%3};"
        : "+f"(c[0]), "+f"(c[1]), "+f"(c[2]), "+f"(c[3])
        : "r"(a0), "r"(a1), "r"(a2), "r"(a3), "r"(b0), "r"(b1));
}

extern __shared__ float smem[];

// ================== Prep: split weights into bf16 hi/lo ==================
__global__ __launch_bounds__(256, 4)
void split_kernel(const float* __restrict__ W_in,
                  const float* __restrict__ W1,
                  const float* __restrict__ W2,
                  const float* __restrict__ W3,
                  const float* __restrict__ W4)
{
    int i = blockIdx.x * 256 + threadIdx.x;
    if (i >= TOT_ELEMS) return;
    float v;
    if (i < WIN_ELEMS) {
        v = W_in[i];
    } else {
        int j = i - WIN_ELEMS;
        int b = j >> 14;
        int o = j & (WB_ELEMS - 1);
        v = (b == 0 ? W1 : b == 1 ? W2 : b == 2 ? W3 : W4)[o];
    }
    unsigned short h = f2bf(v);
    float lo = v - __uint_as_float(((uint32_t)h) << 16);
    g_wh[i] = h;
    g_wl[i] = f2bf(lo);
}

// ================== Main: phase0 + 4 implicit blocks + softmax ==================
// grid 256 CTAs x 8 rows, 256 threads (8 warps; warp = one 16-unit M-tile)
__global__ __launch_bounds__(NTHREADS, 2)
void blocks_kernel(const float* __restrict__ x,
                   const float* __restrict__ b_in,
                   const float* __restrict__ W_out,
                   const float* __restrict__ b_out,
                   float* __restrict__ out)
{
    const int tid  = threadIdx.x;
    const int row0 = blockIdx.x * 8;

    char* smem_c = (char*)smem;
    const uint32_t sbase = smem_u32(smem);
    const uint32_t sWls  = sbase + WLS_BYTE;

    float* bufX = (float*)(smem_c + BUFX_BYTE);
    float* sEpi = (float*)(smem_c + WLS_BYTE);

    const int lane = tid & 31;
    const int warp = tid >> 5;     // = M-tile index (0..7)
    const int g    = lane >> 2;
    const int t    = lane & 3;

    const int      l0 = 8 * t + (g >> 1);
    const uint32_t hb = (uint32_t)(g & 1) * 2;

    // =========== Phase 0 (fused): xf = x @ W_in^T + b_in via HMMA ===========
    float xf[4];
    {
        int m = warp * 16 + g;
        float b0 = b_in[m], b1 = b_in[m + 8];
        xf[0] = b0;  xf[1] = b0;
        xf[2] = b1;  xf[3] = b1;
    }
    {
        const float* xp_base = x + (row0 + g) * 784 + 2 * t;
        #pragma unroll 7
        for (int kt = 0; kt < 49; ++kt) {
            const int k0 = kt * 16;
            float2 xv0 = *(const float2*)(xp_base + k0);
            float2 xv1 = *(const float2*)(xp_base + k0 + 8);
            uint32_t bh0 = bfpack(xv0.x, xv0.y);
            uint32_t bh1 = bfpack(xv1.x, xv1.y);
            float e0 = xv0.x - __uint_as_float(bh0 << 16);
            float e1 = xv0.y - __uint_as_float(bh0 & 0xFFFF0000u);
            float e2 = xv1.x - __uint_as_float(bh1 << 16);
            float e3 = xv1.y - __uint_as_float(bh1 & 0xFFFF0000u);
            uint32_t bl0 = bfpack(e0, e1);
            uint32_t bl1 = bfpack(e2, e3);
            uint32_t ah[4], al[4];
            #pragma unroll
            for (int r = 0; r < 4; ++r) {
                int m  = warp * 16 + g + ((r & 1) << 3);
                int kk = k0 + ((r >> 1) << 3) + 2 * t;
                ah[r] = *(const uint32_t*)&g_wh[m * 784 + kk];
                al[r] = *(const uint32_t*)&g_wl[m * 784 + kk];
            }
            mma_bf16(xf, ah[0], ah[1], ah[2], ah[3], bh0, bh1);
            mma_bf16(xf, ah[0], ah[1], ah[2], ah[3], bl0, bl1);
            mma_bf16(xf, al[0], al[1], al[2], al[3], bh0, bh1);
        }
    }

    // =========== 4 implicit blocks ===========
    uint32_t wh[8][4];
    float zv[4];

    for (int blk = 0; blk < 4; ++blk) {
        const unsigned short* whb = g_wh + WIN_ELEMS + blk * WB_ELEMS;
        const unsigned short* wlb = g_wl + WIN_ELEMS + blk * WB_ELEMS;

        // ---- W fragments: Wh -> regs, Wl -> M-tile-private smem ----
        #pragma unroll
        for (int kt = 0; kt < 8; ++kt) {
            uint32_t wlv[4];
            #pragma unroll
            for (int r = 0; r < 4; ++r) {
                int m  = warp * 16 + g + ((r & 1) << 3);
                int kk = kt * 16 + ((r >> 1) << 3) + 2 * t;
                wh[kt][r] = *(const uint32_t*)&whb[m * 128 + kk];
                wlv[r]    = *(const uint32_t*)&wlb[m * 128 + kk];
            }
            uint32_t wadr = sWls + (uint32_t)(((warp * 8 + kt) * 32 + lane) * 16);
            asm volatile("st.shared.v4.b32 [%0], {%1,%2,%3,%4};"
                         :: "r"(wadr), "r"(wlv[0]), "r"(wlv[1]), "r"(wlv[2]), "r"(wlv[3])
                         : "memory");
        }

        // ---- z0 = tanh(x) -> ZB buffer 0 ----
        #pragma unroll
        for (int e = 0; e < 4; ++e) zv[e] = fast_tanh(xf[e]);

        {
            uint32_t base = (uint32_t)(warp * 256);
            #pragma unroll
            for (int e = 0; e < 4; ++e) {
                float zz = zv[e];
                unsigned short h = f2bf(zz);
                float lo = zz - __uint_as_float(((uint32_t)h) << 16);
                unsigned short l = f2bf(lo);
                uint32_t off = base + (uint32_t)(((e & 1) ? l0 + 4 : l0) * 8)
                             + (uint32_t)((e >> 1) * 4) + hb;
                asm volatile("st.shared.b16 [%0], %1;" :: "r"(sbase + ZBH0_BYTE + off), "h"(h) : "memory");
                asm volatile("st.shared.b16 [%0], %1;" :: "r"(sbase + ZBL0_BYTE + off), "h"(l) : "memory");
            }
        }
        __syncthreads();

        // ---- Picard iterations, ping-pong ZB, 1 barrier/iter ----
        for (int it = 0; it < N_ITER; ++it) {
            const uint32_t rb = (it & 1) ? 4096u : 0u;
            const uint32_t wb = (it & 1) ? 0u : 4096u;
            float acc[4];
            #pragma unroll
            for (int e = 0; e < 4; ++e) acc[e] = xf[e];

            #pragma unroll
            for (int kt = 0; kt < 8; ++kt) {
                uint32_t zh0, zh1, zl0, zl1;
                uint32_t off = (uint32_t)((kt * 32 + lane) * 8);
                asm volatile("ld.shared.v2.b32 {%0,%1}, [%2];"
                             : "=r"(zh0), "=r"(zh1) : "r"(sbase + ZBH0_BYTE + rb + off));
                asm volatile("ld.shared.v2.b32 {%0,%1}, [%2];"
                             : "=r"(zl0), "=r"(zl1) : "r"(sbase + ZBL0_BYTE + rb + off));
                uint32_t wl0, wl1, wl2, wl3;
                uint32_t wadr = sWls + (uint32_t)(((warp * 8 + kt) * 32 + lane) * 16);
                asm volatile("ld.shared.v4.b32 {%0,%1,%2,%3}, [%4];"
                             : "=r"(wl0), "=r"(wl1), "=r"(wl2), "=r"(wl3)
                             : "r"(wadr));
                mma_bf16(acc, wh[kt][0], wh[kt][1], wh[kt][2], wh[kt][3], zh0, zh1);
                mma_bf16(acc, wh[kt][0], wh[kt][1], wh[kt][2], wh[kt][3], zl0, zl1);
                mma_bf16(acc, wl0, wl1, wl2, wl3, zh0, zh1);
            }

            #pragma unroll
            for (int e = 0; e < 4; ++e)
                zv[e] = fast_tanh(acc[e]);

            if (it < N_ITER - 1) {
                uint32_t base = (uint32_t)(warp * 256);
                #pragma unroll
                for (int e = 0; e < 4; ++e) {
                    float zz = zv[e];
                    unsigned short h = f2bf(zz);
                    float lo = zz - __uint_as_float(((uint32_t)h) << 16);
                    unsigned short l = f2bf(lo);
                    uint32_t off = base + (uint32_t)(((e & 1) ? l0 + 4 : l0) * 8)
                                 + (uint32_t)((e >> 1) * 4) + hb;
                    asm volatile("st.shared.b16 [%0], %1;"
                                 :: "r"(sbase + ZBH0_BYTE + wb + off), "h"(h) : "memory");
                    asm volatile("st.shared.b16 [%0], %1;"
                                 :: "r"(sbase + ZBL0_BYTE + wb + off), "h"(l) : "memory");
                }
                __syncthreads();
            }
        }

        #pragma unroll
        for (int e = 0; e < 4; ++e) xf[e] = zv[e];
        __syncthreads();   // all ZB reads done before next block's z0 store / Wl overwrite
    }

    // ---- final z -> bufX ----
    {
        int m0 = warp * 16 + g;
        int n0 = 2 * t;
        *(float2*)&bufX[m0 * BXS + n0]       = make_float2(zv[0], zv[1]);
        *(float2*)&bufX[(m0 + 8) * BXS + n0] = make_float2(zv[2], zv[3]);
    }
    __syncthreads();

    // ---- epilogue: logits + softmax (8 rows) ----
    for (int idx = tid; idx < 10 * UNITS; idx += NTHREADS) sEpi[idx] = W_out[idx];
    if (tid < 10) sEpi[1280 + tid] = b_out[tid];
    __syncthreads();
    float* slog = sEpi + 1296;   // [o][r], 80 floats
    if (tid < 80) {
        int o = tid >> 3;
        int r = tid & 7;
        float acc = sEpi[1280 + o];
        #pragma unroll 8
        for (int k = 0; k < UNITS; ++k)
            acc += bufX[k * BXS + r] * sEpi[o * UNITS + k];
        slog[o * 8 + r] = acc;
    }
    __syncthreads();
    if (tid < 8) {
        int r = tid;
        float l[10];
        float m = -INFINITY;
        #pragma unroll
        for (int o = 0; o < 10; ++o) { l[o] = slog[o * 8 + r]; m = fmaxf(m, l[o]); }
        float s = 0.f;
        #pragma unroll
        for (int o = 0; o < 10; ++o) { l[o] = expf(l[o] - m); s += l[o]; }
        float inv = 1.f / s;
        #pragma unroll
        for (int o = 0; o < 10; ++o) out[(row0 + r) * 10 + o] = l[o] * inv;
    }
}

extern "C" void kernel_launch(void* const* d_in, const int* in_sizes, int n_in,
                              void* d_out, int out_size)
{
    const float* x     = (const float*)d_in[0];
    const float* W_in  = (const float*)d_in[1];
    const float* b_in  = (const float*)d_in[2];
    const float* W1    = (const float*)d_in[3];
    const float* W2    = (const float*)d_in[4];
    const float* W3    = (const float*)d_in[5];
    const float* W4    = (const float*)d_in[6];
    const float* W_out = (const float*)d_in[7];
    const float* b_out = (const float*)d_in[8];
    float* out = (float*)d_out;

    cudaFuncSetAttribute(blocks_kernel,
                         cudaFuncAttributeMaxDynamicSharedMemorySize, K2_SMEM_BYTES);

    split_kernel<<<(TOT_ELEMS + 255) / 256, 256>>>(W_in, W1, W2, W3, W4);
    blocks_kernel<<<256, NTHREADS, K2_SMEM_BYTES>>>(x, b_in, W_out, b_out, out);
}